// round 4
// baseline (speedup 1.0000x reference)
#include <cuda_runtime.h>
#include <cuda_bf16.h>

// Problem constants
#define A_DIM 512      // feature dim
#define C_DIM 345      // classes
#define N_DIM 128      // batch
#define CPAD  384      // padded class dim for scratch
#define MT    128      // c-tile per block
#define NBT   128      // b-tile (columns of Sigma)
#define KT    16       // k-chunk

// Scratch (device globals; no allocation allowed)
__device__ float g_aug[N_DIM * CPAD];
__device__ float g_nll[N_DIM];

// ---------------------------------------------------------------------------
// Label dtype detection: reference declares int64, but JAX without x64 silently
// produces int32. If the buffer is int32, interpreting pairs as int64 yields
// values >= 2^32 (unless every odd label is 0, p ~ (1/345)^64 ~ 0).
// Reads only the first 512 bytes, valid for both layouts (128*4 or 128*8).
// ---------------------------------------------------------------------------
__device__ __forceinline__ int label_is64(const void* lp) {
    const long long* p = (const long long*)lp;
    int ok = 1;
#pragma unroll 1
    for (int i = 0; i < 64; i++) {
        long long v = p[i];
        if (v < 0 || v >= C_DIM) { ok = 0; break; }
    }
    return ok;
}
__device__ __forceinline__ int get_label(const void* lp, int n, int is64) {
    return is64 ? (int)((const long long*)lp)[n] : ((const int*)lp)[n];
}

// ---------------------------------------------------------------------------
// Kernel 1: aug[n, c] = y_s[n,c] + 0.5*Lambda*quad[n,c] + Lambda*lin[n,c]
//   quad[n,c] = sum_{a,b} d[c,a] * Sigma_l[a,b] * d[c,b],  d[c,:] = W[c]-W[l]
//   lin[n,c]  = sum_a d[c,a] * (mean_t[l,a]-mean_s[l,a])
// Block = (c-tile of 128) x (one n). 256 threads, 8x8 frags, f32x2 FFMA core.
// ---------------------------------------------------------------------------
__global__ __launch_bounds__(256, 2)
void aug_kernel(const float* __restrict__ W,
                const float* __restrict__ ys,
                const void*  __restrict__ labels,
                const float* __restrict__ Lam_p,
                const float* __restrict__ ms,
                const float* __restrict__ mt,
                const float* __restrict__ cov) {
    __shared__ float Wl[A_DIM];
    __shared__ float dM[A_DIM];
    __shared__ float As[KT][132];   // d-tile transposed [k][c], padded (16B-aligned rows)
    __shared__ float Bs[KT][NBT];   // Sigma tile [k][b]
    __shared__ float red[16][MT];   // reductions
    __shared__ float linsh[MT];

    const int n  = blockIdx.y;
    const int c0 = blockIdx.x * MT;
    const int t  = threadIdx.x;
    const int tx = t & 15;          // c-fragment selector (8 rows)
    const int ty = t >> 4;          // b-fragment selector (8 cols)

    const int is64 = label_is64(labels);
    const int l = get_label(labels, n, is64);

    for (int i = t; i < A_DIM; i += 256) {
        Wl[i] = W[(size_t)l * A_DIM + i];
        dM[i] = mt[(size_t)l * A_DIM + i] - ms[(size_t)l * A_DIM + i];
    }
    __syncthreads();

    // ---- linear term: lin[c] = sum_a (W[c,a]-Wl[a]) * dM[a] ----
    {
        const int cl  = t & 127;
        const int seg = t >> 7;                 // 0 or 1: half of the a-range
        const int c   = c0 + cl;
        float s = 0.f;
        if (c < C_DIM) {
            const float* wr = W + (size_t)c * A_DIM + seg * 256;
            const float* wl = Wl + seg * 256;
            const float* dm = dM + seg * 256;
#pragma unroll 8
            for (int a = 0; a < 256; a++) s += (wr[a] - wl[a]) * dm[a];
        }
        red[seg][cl] = s;
        __syncthreads();
        if (t < MT) linsh[t] = red[0][t] + red[1][t];
        __syncthreads();
    }

    const float* Sig = cov + (size_t)l * (A_DIM * A_DIM);

    float psum[8];
#pragma unroll
    for (int i = 0; i < 8; i++) psum[i] = 0.f;

    for (int b0 = 0; b0 < A_DIM; b0 += NBT) {
        unsigned long long acc[8][4];           // 8 c-rows x 4 b-pairs (f32x2)
#pragma unroll
        for (int i = 0; i < 8; i++)
#pragma unroll
            for (int j = 0; j < 4; j++) acc[i][j] = 0ULL;

        for (int a0 = 0; a0 < A_DIM; a0 += KT) {
            // Stage d-tile into As[k][c] (transposed). 2 passes x float4.
#pragma unroll
            for (int p = 0; p < 2; p++) {
                const int c  = (t >> 2) + p * 64;
                const int k4 = (t & 3) * 4;
                const int cg = c0 + c;
                float4 d4 = make_float4(0.f, 0.f, 0.f, 0.f);
                if (cg < C_DIM) {
                    const float4 w4 = *(const float4*)(W + (size_t)cg * A_DIM + a0 + k4);
                    d4.x = w4.x - Wl[a0 + k4 + 0];
                    d4.y = w4.y - Wl[a0 + k4 + 1];
                    d4.z = w4.z - Wl[a0 + k4 + 2];
                    d4.w = w4.w - Wl[a0 + k4 + 3];
                }
                As[k4 + 0][c] = d4.x;
                As[k4 + 1][c] = d4.y;
                As[k4 + 2][c] = d4.z;
                As[k4 + 3][c] = d4.w;
            }
            // Stage Sigma tile into Bs[k][b]. Fully coalesced.
#pragma unroll
            for (int p = 0; p < 2; p++) {
                const int r  = (t >> 5) + p * 8;
                const int b4 = (t & 31) * 4;
                *(float4*)&Bs[r][b4] =
                    *(const float4*)(Sig + (size_t)(a0 + r) * A_DIM + b0 + b4);
            }
            __syncthreads();

#pragma unroll
            for (int k = 0; k < KT; k++) {
                const float4 af0 = *(const float4*)&As[k][tx * 8];
                const float4 af1 = *(const float4*)&As[k][tx * 8 + 4];
                const float4 bf0 = *(const float4*)&Bs[k][ty * 8];
                const float4 bf1 = *(const float4*)&Bs[k][ty * 8 + 4];
                unsigned long long bp[4];
                asm("mov.b64 %0,{%1,%2};" : "=l"(bp[0]) : "f"(bf0.x), "f"(bf0.y));
                asm("mov.b64 %0,{%1,%2};" : "=l"(bp[1]) : "f"(bf0.z), "f"(bf0.w));
                asm("mov.b64 %0,{%1,%2};" : "=l"(bp[2]) : "f"(bf1.x), "f"(bf1.y));
                asm("mov.b64 %0,{%1,%2};" : "=l"(bp[3]) : "f"(bf1.z), "f"(bf1.w));
                const float av[8] = {af0.x, af0.y, af0.z, af0.w,
                                     af1.x, af1.y, af1.z, af1.w};
#pragma unroll
                for (int i = 0; i < 8; i++) {
                    unsigned long long ad;
                    asm("mov.b64 %0,{%1,%1};" : "=l"(ad) : "f"(av[i]));
#pragma unroll
                    for (int j = 0; j < 4; j++) {
                        asm("fma.rn.f32x2 %0,%1,%2,%0;"
                            : "+l"(acc[i][j]) : "l"(ad), "l"(bp[j]));
                    }
                }
            }
            __syncthreads();
        }

        // Epilogue for this b-tile: psum[i] += sum_b t[c,b] * d[c,b]
#pragma unroll
        for (int i = 0; i < 8; i++) {
            const int c = c0 + tx * 8 + i;
            if (c < C_DIM) {
                const float* wr  = W + (size_t)c * A_DIM + b0 + ty * 8;
                const float* wlr = Wl + b0 + ty * 8;
                const float4 w4a = *(const float4*)wr;
                const float4 w4b = *(const float4*)(wr + 4);
                const float db[8] = {w4a.x - wlr[0], w4a.y - wlr[1],
                                     w4a.z - wlr[2], w4a.w - wlr[3],
                                     w4b.x - wlr[4], w4b.y - wlr[5],
                                     w4b.z - wlr[6], w4b.w - wlr[7]};
#pragma unroll
                for (int j = 0; j < 4; j++) {
                    float lo, hi;
                    asm("mov.b64 {%0,%1},%2;" : "=f"(lo), "=f"(hi) : "l"(acc[i][j]));
                    psum[i] += lo * db[2 * j] + hi * db[2 * j + 1];
                }
            }
        }
    }

    __syncthreads();
#pragma unroll
    for (int i = 0; i < 8; i++) red[ty][tx * 8 + i] = psum[i];
    __syncthreads();

    if (t < MT) {
        float s = 0.f;
#pragma unroll
        for (int r = 0; r < 16; r++) s += red[r][t];
        const int c = c0 + t;
        if (c < C_DIM) {
            const float Lam = Lam_p[0];
            g_aug[n * CPAD + c] =
                ys[n * C_DIM + c] + 0.5f * Lam * s + Lam * linsh[t];
        }
    }
}

// ---------------------------------------------------------------------------
// Kernel 2: per-n NLL via log-softmax (deterministic tree reductions)
// ---------------------------------------------------------------------------
__global__ void nll_kernel(const void* __restrict__ labels) {
    __shared__ float sm[128];
    const int n = blockIdx.x;
    const int t = threadIdx.x;

    const float v0 = g_aug[n * CPAD + t];
    const float v1 = g_aug[n * CPAD + t + 128];
    const float v2 = (t + 256 < C_DIM) ? g_aug[n * CPAD + t + 256] : -1e30f;

    float mx = fmaxf(v0, fmaxf(v1, v2));
    sm[t] = mx;
    __syncthreads();
    for (int s = 64; s > 0; s >>= 1) {
        if (t < s) sm[t] = fmaxf(sm[t], sm[t + s]);
        __syncthreads();
    }
    const float MX = sm[0];
    __syncthreads();

    float e = expf(v0 - MX) + expf(v1 - MX);
    if (t + 256 < C_DIM) e += expf(v2 - MX);
    sm[t] = e;
    __syncthreads();
    for (int s = 64; s > 0; s >>= 1) {
        if (t < s) sm[t] += sm[t + s];
        __syncthreads();
    }
    if (t == 0) {
        const int is64 = label_is64(labels);
        const int l = get_label(labels, n, is64);
        g_nll[n] = logf(sm[0]) + MX - g_aug[n * CPAD + l];
    }
}

// ---------------------------------------------------------------------------
// Kernel 3: mean over N
// ---------------------------------------------------------------------------
__global__ void mean_kernel(float* __restrict__ out) {
    __shared__ float sm[128];
    const int t = threadIdx.x;
    sm[t] = g_nll[t];
    __syncthreads();
    for (int s = 64; s > 0; s >>= 1) {
        if (t < s) sm[t] += sm[t + s];
        __syncthreads();
    }
    if (t == 0) out[0] = sm[0] * (1.0f / (float)N_DIM);
}

// ---------------------------------------------------------------------------
// Inputs (metadata order):
// 0 fc_weight [345,512] f32, 1 features_source [128,512] f32 (unused),
// 2 y_s [128,345] f32, 3 labels_source [128] i64/i32, 4 Lambda [1] f32,
// 5 mean_source [345,512] f32, 6 mean_target [345,512] f32,
// 7 covariance_target [345,512,512] f32. Output: scalar f32.
// ---------------------------------------------------------------------------
extern "C" void kernel_launch(void* const* d_in, const int* in_sizes, int n_in,
                              void* d_out, int out_size) {
    const float* W      = (const float*)d_in[0];
    const float* ys     = (const float*)d_in[2];
    const void*  labels = d_in[3];
    const float* Lam    = (const float*)d_in[4];
    const float* ms     = (const float*)d_in[5];
    const float* mt     = (const float*)d_in[6];
    const float* cov    = (const float*)d_in[7];
    float* out = (float*)d_out;

    aug_kernel<<<dim3(3, N_DIM), 256>>>(W, ys, labels, Lam, ms, mt, cov);
    nll_kernel<<<N_DIM, 128>>>(labels);
    mean_kernel<<<1, 128>>>(out);
}

// round 6
// speedup vs baseline: 3.7853x; 3.7853x over previous
#include <cuda_runtime.h>
#include <cuda_bf16.h>
#include <cstdint>

#define A_DIM 512
#define C_DIM 345
#define N_DIM 128
#define CPAD  384

// ---------------------------------------------------------------------------
// Scratch (device globals; no allocation allowed)
// ---------------------------------------------------------------------------
__device__ __align__(1024) __nv_bfloat16 g_covT[(size_t)N_DIM * A_DIM * A_DIM]; // [slot][b][a] 67MB
__device__ __align__(1024) __nv_bfloat16 g_Wbf[CPAD * A_DIM];                   // bf16 W, padded rows
__device__ float g_v[N_DIM * A_DIM];      // v[slot][b] = W_l^T Sigma_l
__device__ float g_f[N_DIM * CPAD];       // f[slot][c] = 0.5*Lam*quad + Lam*lin
__device__ float g_nll[N_DIM];
__device__ int   g_slot[N_DIM];
__device__ int   g_first[N_DIM];

// ---------------------------------------------------------------------------
// Helpers
// ---------------------------------------------------------------------------
__device__ __forceinline__ uint32_t smem_u32(const void* p) {
    uint32_t a;
    asm("{ .reg .u64 t; cvta.to.shared.u64 t, %1; cvt.u32.u64 %0, t; }" : "=r"(a) : "l"(p));
    return a;
}
__device__ __forceinline__ void cp16(uint32_t dst, const void* src) {
    asm volatile("cp.async.cg.shared.global [%0], [%1], 16;" :: "r"(dst), "l"(src));
}
#define CP_COMMIT() asm volatile("cp.async.commit_group;")
#define CP_WAIT(N)  asm volatile("cp.async.wait_group %0;" :: "n"(N))

#define LDSM4(r0, r1, r2, r3, addr)                                            \
    asm volatile("ldmatrix.sync.aligned.m8n8.x4.shared.b16 {%0,%1,%2,%3}, [%4];" \
        : "=r"(r0), "=r"(r1), "=r"(r2), "=r"(r3) : "r"(addr))

#define MMA16816(d, a, b0, b1)                                                 \
    asm volatile("mma.sync.aligned.m16n8k16.row.col.f32.bf16.bf16.f32 "        \
        "{%0,%1,%2,%3},{%4,%5,%6,%7},{%8,%9},{%0,%1,%2,%3};"                   \
        : "+f"((d)[0]), "+f"((d)[1]), "+f"((d)[2]), "+f"((d)[3])               \
        : "r"((a)[0]), "r"((a)[1]), "r"((a)[2]), "r"((a)[3]), "r"(b0), "r"(b1))

// Label dtype detection (jax may emit int32 or int64)
__device__ __forceinline__ int label_is64(const void* lp) {
    const long long* p = (const long long*)lp;
    int ok = 1;
#pragma unroll 1
    for (int i = 0; i < 64; i++) {
        long long v = p[i];
        if (v < 0 || v >= C_DIM) { ok = 0; break; }
    }
    return ok;
}
__device__ __forceinline__ int get_label(const void* lp, int n, int is64) {
    return is64 ? (int)((const long long*)lp)[n] : ((const int*)lp)[n];
}

// ---------------------------------------------------------------------------
// prep: slot/first tables
// ---------------------------------------------------------------------------
__global__ void prep_labels(const void* __restrict__ labels) {
    const int t = threadIdx.x;
    const int is64 = label_is64(labels);
    const int ln = get_label(labels, t, is64);
    int slot = t, first = 1;
    for (int m = 0; m < t; m++)
        if (get_label(labels, m, is64) == ln) { slot = m; first = 0; break; }
    g_slot[t] = slot;
    g_first[t] = first;
}

// cast W -> bf16 (pad rows >= C_DIM with zeros)
__global__ void conv_w(const float* __restrict__ Wg) {
    const int c = blockIdx.x, t = threadIdx.x;
    __nv_bfloat162 val;
    if (c < C_DIM) {
        const float2 w = *(const float2*)(Wg + (size_t)c * A_DIM + 2 * t);
        val = __floats2bfloat162_rn(w.x, w.y);
    } else {
        val = __floats2bfloat162_rn(0.f, 0.f);
    }
    *(__nv_bfloat162*)(g_Wbf + (size_t)c * A_DIM + 2 * t) = val;
}

// transpose+cast Sigma_l -> covT[slot][b][a] bf16 for first-occurrence slots
__global__ void conv_cov(const float* __restrict__ cov, const void* __restrict__ labels) {
    const int n = blockIdx.z;
    if (!g_first[n]) return;
    __shared__ int s_l;
    if (threadIdx.x == 0 && threadIdx.y == 0)
        s_l = get_label(labels, n, label_is64(labels));
    __syncthreads();
    const int l = s_l;

    __shared__ float tile[64][65];
    const int a0 = blockIdx.y * 64, b0 = blockIdx.x * 64;
    const float* S = cov + (size_t)l * A_DIM * A_DIM;
    for (int r = threadIdx.y; r < 64; r += 4)
        tile[r][threadIdx.x] = S[(size_t)(a0 + r) * A_DIM + b0 + threadIdx.x];
    __syncthreads();
    const int t = threadIdx.y * 64 + threadIdx.x;
    const int i = t & 31;
#pragma unroll
    for (int j = t >> 5; j < 64; j += 8) {
        *(__nv_bfloat162*)(g_covT + ((size_t)n * A_DIM + b0 + j) * A_DIM + a0 + 2 * i) =
            __floats2bfloat162_rn(tile[2 * i][j], tile[2 * i + 1][j]);
    }
}

// v[slot][b] = sum_a W[l][a] * Sigma[a][b] = dot(covT[slot][b][:], W[l][:])
__global__ void v_kernel(const float* __restrict__ Wg, const void* __restrict__ labels) {
    const int n = blockIdx.y;
    if (!g_first[n]) return;
    __shared__ float sWl[A_DIM];
    __shared__ int s_l;
    const int t = threadIdx.x;
    if (t == 0) s_l = get_label(labels, n, label_is64(labels));
    __syncthreads();
    const int l = s_l;
    for (int a = t; a < A_DIM; a += 256) sWl[a] = Wg[(size_t)l * A_DIM + a];
    __syncthreads();

    const int w = t >> 5, lane = t & 31;
#pragma unroll 1
    for (int r = 0; r < 16; r++) {
        const int b = blockIdx.x * 128 + w * 16 + r;
        const __nv_bfloat162* row =
            (const __nv_bfloat162*)(g_covT + ((size_t)n * A_DIM + b) * A_DIM);
        float s = 0.f;
#pragma unroll
        for (int jj = 0; jj < 8; jj++) {
            const float2 f = __bfloat1622float2(row[lane + 32 * jj]);
            s += f.x * sWl[2 * (lane + 32 * jj)] + f.y * sWl[2 * (lane + 32 * jj) + 1];
        }
#pragma unroll
        for (int o = 16; o > 0; o >>= 1) s += __shfl_xor_sync(~0u, s, o);
        if (lane == 0) g_v[n * A_DIM + b] = s;
    }
}

// ---------------------------------------------------------------------------
// Main HMMA GEMM: per (c-tile, first-slot n): f[n][c] = 0.5L*quad + L*lin
//   P = Wbf(c-tile) x SigmaT(slot), contracted in-register against fp32 data.
// ---------------------------------------------------------------------------
#define STG_A   0                       // 3 x 8192
#define STG_B   24576                   // 3 x 8192
#define OFF_WL  49152
#define OFF_V   (OFF_WL + 2048)
#define OFF_DM  (OFF_V + 2048)
#define OFF_Q   (OFF_DM + 2048)         // 128*2 f32
#define OFF_L   (OFF_Q + 1024)
#define OFF_LBL (OFF_L + 1024)
#define SMEM_DYN (OFF_LBL + 16)

__global__ __launch_bounds__(256, 2)
void gemm_kernel(const float* __restrict__ Wg,
                 const void*  __restrict__ labels,
                 const float* __restrict__ Lam_p,
                 const float* __restrict__ ms,
                 const float* __restrict__ mt) {
    extern __shared__ __align__(128) char dsm[];
    const int n = blockIdx.y;
    if (!g_first[n]) return;

    const uint32_t sb = smem_u32(dsm);
    float* sWl = (float*)(dsm + OFF_WL);
    float* sV  = (float*)(dsm + OFF_V);
    float* sDM = (float*)(dsm + OFF_DM);
    float* sQ  = (float*)(dsm + OFF_Q);
    float* sL  = (float*)(dsm + OFF_L);
    int*   sLb = (int*)(dsm + OFF_LBL);

    const int c0 = blockIdx.x * 128;
    const int t = threadIdx.x;
    const int lane = t & 31, w = t >> 5;
    const int wm = w & 3, wn = w >> 2;

    if (t == 0) sLb[0] = get_label(labels, n, label_is64(labels));
    __syncthreads();
    const int l = sLb[0];
    for (int a = t; a < A_DIM; a += 256) {
        sWl[a] = Wg[(size_t)l * A_DIM + a];
        sV[a]  = g_v[n * A_DIM + a];
        sDM[a] = mt[(size_t)l * A_DIM + a] - ms[(size_t)l * A_DIM + a];
    }
    __syncthreads();

    // per-lane ldmatrix geometry
    const int lj = lane >> 3, li = lane & 7;
    const int amr0 = wm * 32 + (lj & 1) * 8 + li;  // mi=0 row; mi=1 adds 16
    const int amr1 = amr0 + 16;
    const int akc  = lj >> 1;                      // + 2*s
    const int asw0 = (amr0 >> 1) & 3, asw1 = (amr1 >> 1) & 3;
    int bnr[4], bsw[4];
#pragma unroll
    for (int np = 0; np < 4; np++) {
        bnr[np] = wn * 64 + np * 16 + (lj >> 1) * 8 + li;
        bsw[np] = (bnr[np] >> 1) & 3;
    }
    const int bkc = lj & 1;                        // + 2*s

    float qacc[4] = {0, 0, 0, 0}, lacc[4] = {0, 0, 0, 0};
    const float Lam = Lam_p[0];

#pragma unroll 1
    for (int bi = 0; bi < 4; bi++) {
        float D[2][8][4];
#pragma unroll
        for (int mi = 0; mi < 2; mi++)
#pragma unroll
            for (int ni = 0; ni < 8; ni++)
#pragma unroll
                for (int e = 0; e < 4; e++) D[mi][ni][e] = 0.f;

        // stage helper (inline): chunk ck -> stage st
        auto stage = [&](int st, int ck) {
            const int a0 = ck * 32;
#pragma unroll
            for (int p = 0; p < 2; p++) {
                const int id = t + 256 * p;
                const int m = id >> 2, ch = id & 3;
                const uint32_t so = (uint32_t)(m * 64 + ((ch ^ ((m >> 1) & 3)) << 4));
                cp16(sb + STG_A + st * 8192 + so,
                     g_Wbf + (size_t)(c0 + m) * A_DIM + a0 + ch * 8);
                cp16(sb + STG_B + st * 8192 + so,
                     g_covT + ((size_t)n * A_DIM + bi * 128 + m) * A_DIM + a0 + ch * 8);
            }
            CP_COMMIT();
        };

        stage(0, 0); stage(1, 1); stage(2, 2);

        int st = 0;
#pragma unroll 1
        for (int k = 0; k < 16; k++) {
            if (k < 14) CP_WAIT(2);
            else if (k == 14) CP_WAIT(1);
            else CP_WAIT(0);
            __syncthreads();

            const uint32_t Ab = sb + STG_A + st * 8192;
            const uint32_t Bb = sb + STG_B + st * 8192;
#pragma unroll
            for (int s = 0; s < 2; s++) {
                uint32_t a0r[4], a1r[4], br[4][4];
                LDSM4(a0r[0], a0r[1], a0r[2], a0r[3],
                      Ab + amr0 * 64 + (((2 * s + akc) ^ asw0) << 4));
                LDSM4(a1r[0], a1r[1], a1r[2], a1r[3],
                      Ab + amr1 * 64 + (((2 * s + akc) ^ asw1) << 4));
#pragma unroll
                for (int np = 0; np < 4; np++)
                    LDSM4(br[np][0], br[np][1], br[np][2], br[np][3],
                          Bb + bnr[np] * 64 + (((2 * s + bkc) ^ bsw[np]) << 4));
#pragma unroll
                for (int ni = 0; ni < 8; ni++) {
                    const uint32_t b0 = br[ni >> 1][(ni & 1) * 2];
                    const uint32_t b1 = br[ni >> 1][(ni & 1) * 2 + 1];
                    MMA16816(D[0][ni], a0r, b0, b1);
                    MMA16816(D[1][ni], a1r, b0, b1);
                }
            }
            __syncthreads();
            if (k + 3 < 16) stage(st, k + 3);
            st = (st == 2) ? 0 : st + 1;
        }

        // epilogue: contract P-frags against dw, v, dM
#pragma unroll
        for (int mi = 0; mi < 2; mi++) {
            const int crb = c0 + wm * 32 + mi * 16 + (lane >> 2);
#pragma unroll
            for (int half = 0; half < 2; half++) {
                const int cr = crb + half * 8;
                if (cr < C_DIM) {
                    const float* wrow = Wg + (size_t)cr * A_DIM;
                    float q = 0.f, li2 = 0.f;
#pragma unroll
                    for (int ni = 0; ni < 8; ni++) {
                        const int b = bi * 128 + wn * 64 + ni * 8 + (lane & 3) * 2;
                        const float2 wv = *(const float2*)(wrow + b);
                        const float dw0 = wv.x - sWl[b], dw1 = wv.y - sWl[b + 1];
                        q += (D[mi][ni][half * 2 + 0] - sV[b]) * dw0
                           + (D[mi][ni][half * 2 + 1] - sV[b + 1]) * dw1;
                        li2 += dw0 * sDM[b] + dw1 * sDM[b + 1];
                    }
                    qacc[mi * 2 + half] += q;
                    lacc[mi * 2 + half] += li2;
                }
            }
        }
    }

#pragma unroll
    for (int i = 0; i < 4; i++) {
        qacc[i] += __shfl_xor_sync(~0u, qacc[i], 1);
        qacc[i] += __shfl_xor_sync(~0u, qacc[i], 2);
        lacc[i] += __shfl_xor_sync(~0u, lacc[i], 1);
        lacc[i] += __shfl_xor_sync(~0u, lacc[i], 2);
    }
    if ((lane & 3) == 0) {
#pragma unroll
        for (int i = 0; i < 4; i++) {
            const int row = wm * 32 + (i >> 1) * 16 + (i & 1) * 8 + (lane >> 2);
            sQ[row * 2 + wn] = qacc[i];
            sL[row * 2 + wn] = lacc[i];
        }
    }
    __syncthreads();
    if (t < 128) {
        const int c = c0 + t;
        if (c < C_DIM) {
            const float q = sQ[t * 2] + sQ[t * 2 + 1];
            const float li2 = sL[t * 2] + sL[t * 2 + 1];
            g_f[n * CPAD + c] = 0.5f * Lam * q + Lam * li2;
        }
    }
}

// ---------------------------------------------------------------------------
// NLL + mean
// ---------------------------------------------------------------------------
__global__ void nll_kernel(const float* __restrict__ ys, const void* __restrict__ labels) {
    __shared__ float sm[128];
    const int n = blockIdx.x, t = threadIdx.x;
    const int sl = g_slot[n];
    const float v0 = ys[(size_t)n * C_DIM + t] + g_f[sl * CPAD + t];
    const float v1 = ys[(size_t)n * C_DIM + t + 128] + g_f[sl * CPAD + t + 128];
    const float v2 = (t + 256 < C_DIM)
                   ? ys[(size_t)n * C_DIM + t + 256] + g_f[sl * CPAD + t + 256] : -1e30f;
    float mx = fmaxf(v0, fmaxf(v1, v2));
    sm[t] = mx; __syncthreads();
    for (int s = 64; s > 0; s >>= 1) { if (t < s) sm[t] = fmaxf(sm[t], sm[t + s]); __syncthreads(); }
    const float MX = sm[0]; __syncthreads();
    float e = expf(v0 - MX) + expf(v1 - MX);
    if (t + 256 < C_DIM) e += expf(v2 - MX);
    sm[t] = e; __syncthreads();
    for (int s = 64; s > 0; s >>= 1) { if (t < s) sm[t] += sm[t + s]; __syncthreads(); }
    if (t == 0) {
        const int l = get_label(labels, n, label_is64(labels));
        const float pick = ys[(size_t)n * C_DIM + l] + g_f[sl * CPAD + l];
        g_nll[n] = logf(sm[0]) + MX - pick;
    }
}

__global__ void mean_kernel(float* __restrict__ out) {
    __shared__ float sm[128];
    const int t = threadIdx.x;
    sm[t] = g_nll[t]; __syncthreads();
    for (int s = 64; s > 0; s >>= 1) { if (t < s) sm[t] += sm[t + s]; __syncthreads(); }
    if (t == 0) out[0] = sm[0] * (1.0f / (float)N_DIM);
}

// ---------------------------------------------------------------------------
// Host launcher
// ---------------------------------------------------------------------------
extern "C" void kernel_launch(void* const* d_in, const int* in_sizes, int n_in,
                              void* d_out, int out_size) {
    const float* W      = (const float*)d_in[0];
    const float* ys     = (const float*)d_in[2];
    const void*  labels = d_in[3];
    const float* Lam    = (const float*)d_in[4];
    const float* ms     = (const float*)d_in[5];
    const float* mt     = (const float*)d_in[6];
    const float* cov    = (const float*)d_in[7];
    float* out = (float*)d_out;

    static int attr_set = 0;
    if (!attr_set) {
        cudaFuncSetAttribute(gemm_kernel, cudaFuncAttributeMaxDynamicSharedMemorySize,
                             SMEM_DYN);
        attr_set = 1;
    }

    prep_labels<<<1, N_DIM>>>(labels);
    conv_w<<<CPAD, 256>>>(W);
    conv_cov<<<dim3(8, 8, N_DIM), dim3(64, 4)>>>(cov, labels);
    v_kernel<<<dim3(4, N_DIM), 256>>>(W, labels);
    gemm_kernel<<<dim3(3, N_DIM), 256, SMEM_DYN>>>(W, labels, Lam, ms, mt);
    nll_kernel<<<N_DIM, 128>>>(ys, labels);
    mean_kernel<<<1, 128>>>(out);
}

// round 8
// speedup vs baseline: 4.7099x; 1.2442x over previous
#include <cuda_runtime.h>
#include <cuda_bf16.h>
#include <cstdint>

#define A_DIM 512
#define C_DIM 345
#define N_DIM 128
#define CPAD  384

// ---------------------------------------------------------------------------
// Scratch (device globals; no allocation allowed)
// ---------------------------------------------------------------------------
__device__ __align__(1024) __nv_bfloat16 g_covT[(size_t)N_DIM * A_DIM * A_DIM]; // [slot][b][a] 67MB
__device__ __align__(1024) __nv_bfloat16 g_Wbf[CPAD * A_DIM];                   // bf16 W, padded rows
__device__ float g_f4[4][N_DIM][CPAD];    // partial f per b-chunk
__device__ float g_nll[N_DIM];
__device__ int   g_slot[N_DIM];
__device__ int   g_first[N_DIM];

// ---------------------------------------------------------------------------
// Helpers
// ---------------------------------------------------------------------------
__device__ __forceinline__ uint32_t smem_u32(const void* p) {
    uint32_t a;
    asm("{ .reg .u64 t; cvta.to.shared.u64 t, %1; cvt.u32.u64 %0, t; }" : "=r"(a) : "l"(p));
    return a;
}
__device__ __forceinline__ void cp16(uint32_t dst, const void* src) {
    asm volatile("cp.async.cg.shared.global [%0], [%1], 16;" :: "r"(dst), "l"(src));
}
#define CP_COMMIT() asm volatile("cp.async.commit_group;")
#define CP_WAIT(N)  asm volatile("cp.async.wait_group %0;" :: "n"(N))

#define LDSM4(r0, r1, r2, r3, addr)                                            \
    asm volatile("ldmatrix.sync.aligned.m8n8.x4.shared.b16 {%0,%1,%2,%3}, [%4];" \
        : "=r"(r0), "=r"(r1), "=r"(r2), "=r"(r3) : "r"(addr))

#define MMA16816(d, a, b0, b1)                                                 \
    asm volatile("mma.sync.aligned.m16n8k16.row.col.f32.bf16.bf16.f32 "        \
        "{%0,%1,%2,%3},{%4,%5,%6,%7},{%8,%9},{%0,%1,%2,%3};"                   \
        : "+f"((d)[0]), "+f"((d)[1]), "+f"((d)[2]), "+f"((d)[3])               \
        : "r"((a)[0]), "r"((a)[1]), "r"((a)[2]), "r"((a)[3]), "r"(b0), "r"(b1))

// Label dtype detection (jax may emit int32 or int64)
__device__ __forceinline__ int label_is64(const void* lp) {
    const long long* p = (const long long*)lp;
    int ok = 1;
#pragma unroll 1
    for (int i = 0; i < 64; i++) {
        long long v = p[i];
        if (v < 0 || v >= C_DIM) { ok = 0; break; }
    }
    return ok;
}
__device__ __forceinline__ int get_label(const void* lp, int n, int is64) {
    return is64 ? (int)((const long long*)lp)[n] : ((const int*)lp)[n];
}

// ---------------------------------------------------------------------------
// prep: slot/first tables
// ---------------------------------------------------------------------------
__global__ void prep_labels(const void* __restrict__ labels) {
    const int t = threadIdx.x;
    const int is64 = label_is64(labels);
    const int ln = get_label(labels, t, is64);
    int slot = t, first = 1;
    for (int m = 0; m < t; m++)
        if (get_label(labels, m, is64) == ln) { slot = m; first = 0; break; }
    g_slot[t] = slot;
    g_first[t] = first;
}

// cast W -> bf16 (pad rows >= C_DIM with zeros)
__global__ void conv_w(const float* __restrict__ Wg) {
    const int c = blockIdx.x, t = threadIdx.x;
    __nv_bfloat162 val;
    if (c < C_DIM) {
        const float2 w = *(const float2*)(Wg + (size_t)c * A_DIM + 2 * t);
        val = __floats2bfloat162_rn(w.x, w.y);
    } else {
        val = __floats2bfloat162_rn(0.f, 0.f);
    }
    *(__nv_bfloat162*)(g_Wbf + (size_t)c * A_DIM + 2 * t) = val;
}

// transpose+cast Sigma_l -> covT[slot][b][a] bf16 for first-occurrence slots
__global__ void conv_cov(const float* __restrict__ cov, const void* __restrict__ labels) {
    const int n = blockIdx.z;
    if (!g_first[n]) return;
    __shared__ int s_l;
    if (threadIdx.x == 0 && threadIdx.y == 0)
        s_l = get_label(labels, n, label_is64(labels));
    __syncthreads();
    const int l = s_l;

    __shared__ float tile[64][65];
    const int a0 = blockIdx.y * 64, b0 = blockIdx.x * 64;
    const float* S = cov + (size_t)l * A_DIM * A_DIM;
    for (int r = threadIdx.y; r < 64; r += 4)
        tile[r][threadIdx.x] = S[(size_t)(a0 + r) * A_DIM + b0 + threadIdx.x];
    __syncthreads();
    const int t = threadIdx.y * 64 + threadIdx.x;
    const int i = t & 31;
#pragma unroll
    for (int j = t >> 5; j < 64; j += 8) {
        *(__nv_bfloat162*)(g_covT + ((size_t)n * A_DIM + b0 + j) * A_DIM + a0 + 2 * i) =
            __floats2bfloat162_rn(tile[2 * i][j], tile[2 * i + 1][j]);
    }
}

// ---------------------------------------------------------------------------
// Main HMMA GEMM, b-split: CTA = (c-tile, b-chunk, slot).
//   P_chunk = Wbf(c-tile) x SigmaT(slot, b-chunk)   [128 x 128, K=512]
//   v[b] = sum_a Wl[a] * Sigma[a,b] accumulated from staged B tiles (fp32)
//   g_f4[bi][n][c] = 0.5L * sum_b (P-v) dW + L * sum_b dW dM
// ---------------------------------------------------------------------------
#define STG_A   0                       // 3 x 8192
#define STG_B   24576                   // 3 x 8192
#define OFF_WL  49152                   // 512 f32
#define OFF_DM  (OFF_WL + 2048)
#define OFF_Q   (OFF_DM + 2048)         // 128*2 f32
#define OFF_L   (OFF_Q + 1024)
#define OFF_VP  (OFF_L + 1024)          // 256 f32 v partials
#define OFF_LBL (OFF_VP + 1024)
#define SMEM_DYN (OFF_LBL + 16)

__global__ __launch_bounds__(256, 2)
void gemm_kernel(const float* __restrict__ Wg,
                 const void*  __restrict__ labels,
                 const float* __restrict__ Lam_p,
                 const float* __restrict__ ms,
                 const float* __restrict__ mt) {
    extern __shared__ __align__(128) char dsm[];
    const int n = blockIdx.z;
    if (!g_first[n]) return;
    const int bi = blockIdx.y;

    const uint32_t sb = smem_u32(dsm);
    float* sWl = (float*)(dsm + OFF_WL);
    float* sDM = (float*)(dsm + OFF_DM);
    float* sQ  = (float*)(dsm + OFF_Q);
    float* sL  = (float*)(dsm + OFF_L);
    float* sVP = (float*)(dsm + OFF_VP);
    int*   sLb = (int*)(dsm + OFF_LBL);

    const int c0 = blockIdx.x * 128;
    const int t = threadIdx.x;
    const int lane = t & 31, w = t >> 5;
    const int wm = w & 3, wn = w >> 2;

    if (t == 0) sLb[0] = get_label(labels, n, label_is64(labels));
    __syncthreads();
    const int l = sLb[0];
    for (int a = t; a < A_DIM; a += 256) {
        sWl[a] = Wg[(size_t)l * A_DIM + a];
        sDM[a] = mt[(size_t)l * A_DIM + a] - ms[(size_t)l * A_DIM + a];
    }
    __syncthreads();

    // per-lane ldmatrix geometry
    const int lj = lane >> 3, li = lane & 7;
    const int amr0 = wm * 32 + (lj & 1) * 8 + li;
    const int amr1 = amr0 + 16;
    const int akc  = lj >> 1;
    const int asw0 = (amr0 >> 1) & 3, asw1 = (amr1 >> 1) & 3;
    int bnr[4], bsw[4];
#pragma unroll
    for (int np = 0; np < 4; np++) {
        bnr[np] = wn * 64 + np * 16 + (lj >> 1) * 8 + li;
        bsw[np] = (bnr[np] >> 1) & 3;
    }
    const int bkc = lj & 1;

    // v accumulation geometry: thread -> (row, 2 chunks of 8 bf16)
    const int vrow = t >> 1;
    const int vc0  = (t & 1) * 2;
    const uint32_t vof0 = (uint32_t)(vrow * 64 + (((vc0 + 0) ^ ((vrow >> 1) & 3)) << 4));
    const uint32_t vof1 = (uint32_t)(vrow * 64 + (((vc0 + 1) ^ ((vrow >> 1) & 3)) << 4));

    float D[2][8][4];
#pragma unroll
    for (int mi = 0; mi < 2; mi++)
#pragma unroll
        for (int ni = 0; ni < 8; ni++)
#pragma unroll
            for (int e = 0; e < 4; e++) D[mi][ni][e] = 0.f;
    float vacc = 0.f;

    auto stage = [&](int st, int ck) {
        const int a0 = ck * 32;
#pragma unroll
        for (int p = 0; p < 2; p++) {
            const int id = t + 256 * p;
            const int m = id >> 2, ch = id & 3;
            const uint32_t so = (uint32_t)(m * 64 + ((ch ^ ((m >> 1) & 3)) << 4));
            cp16(sb + STG_A + st * 8192 + so,
                 g_Wbf + (size_t)(c0 + m) * A_DIM + a0 + ch * 8);
            cp16(sb + STG_B + st * 8192 + so,
                 g_covT + ((size_t)n * A_DIM + bi * 128 + m) * A_DIM + a0 + ch * 8);
        }
        CP_COMMIT();
    };

    stage(0, 0); stage(1, 1); stage(2, 2);

    int st = 0;
#pragma unroll 1
    for (int k = 0; k < 16; k++) {
        if (k < 14) CP_WAIT(2);
        else if (k == 14) CP_WAIT(1);
        else CP_WAIT(0);
        __syncthreads();

        const uint32_t Ab = sb + STG_A + st * 8192;
        const uint32_t Bb = sb + STG_B + st * 8192;
#pragma unroll
        for (int s = 0; s < 2; s++) {
            uint32_t a0r[4], a1r[4], br[4][4];
            LDSM4(a0r[0], a0r[1], a0r[2], a0r[3],
                  Ab + amr0 * 64 + (((2 * s + akc) ^ asw0) << 4));
            LDSM4(a1r[0], a1r[1], a1r[2], a1r[3],
                  Ab + amr1 * 64 + (((2 * s + akc) ^ asw1) << 4));
#pragma unroll
            for (int np = 0; np < 4; np++)
                LDSM4(br[np][0], br[np][1], br[np][2], br[np][3],
                      Bb + bnr[np] * 64 + (((2 * s + bkc) ^ bsw[np]) << 4));
#pragma unroll
            for (int ni = 0; ni < 8; ni++) {
                const uint32_t b0 = br[ni >> 1][(ni & 1) * 2];
                const uint32_t b1 = br[ni >> 1][(ni & 1) * 2 + 1];
                MMA16816(D[0][ni], a0r, b0, b1);
                MMA16816(D[1][ni], a1r, b0, b1);
            }
        }
        // v side-accumulation from the staged B tile (fp32)
        {
            const int a0 = k * 32;
            const char* Bp = dsm + STG_B + st * 8192;
            const uint4 p0 = *(const uint4*)(Bp + vof0);
            const uint4 p1 = *(const uint4*)(Bp + vof1);
            const __nv_bfloat162* h0 = (const __nv_bfloat162*)&p0;
            const __nv_bfloat162* h1 = (const __nv_bfloat162*)&p1;
            const float* wl0 = sWl + a0 + vc0 * 8;
#pragma unroll
            for (int j = 0; j < 4; j++) {
                const float2 f0 = __bfloat1622float2(h0[j]);
                const float2 f1 = __bfloat1622float2(h1[j]);
                vacc += f0.x * wl0[2 * j] + f0.y * wl0[2 * j + 1];
                vacc += f1.x * wl0[8 + 2 * j] + f1.y * wl0[8 + 2 * j + 1];
            }
        }
        __syncthreads();
        if (k + 3 < 16) stage(st, k + 3);
        st = (st == 2) ? 0 : st + 1;
    }

    sVP[t] = vacc;
    __syncthreads();

    // epilogue: contract P-frags against dw, v, dM
    float qacc[4] = {0, 0, 0, 0}, lacc[4] = {0, 0, 0, 0};
#pragma unroll
    for (int mi = 0; mi < 2; mi++) {
        const int crb = c0 + wm * 32 + mi * 16 + (lane >> 2);
#pragma unroll
        for (int half = 0; half < 2; half++) {
            const int cr = crb + half * 8;
            if (cr < C_DIM) {
                const float* wrow = Wg + (size_t)cr * A_DIM;
                float q = 0.f, li2 = 0.f;
#pragma unroll
                for (int ni = 0; ni < 8; ni++) {
                    const int bl = wn * 64 + ni * 8 + (lane & 3) * 2;  // local b
                    const int b  = bi * 128 + bl;                      // global b
                    const float2 wv = *(const float2*)(wrow + b);
                    const float dw0 = wv.x - sWl[b], dw1 = wv.y - sWl[b + 1];
                    const float v0 = sVP[2 * bl] + sVP[2 * bl + 1];
                    const float v1 = sVP[2 * bl + 2] + sVP[2 * bl + 3];
                    q += (D[mi][ni][half * 2 + 0] - v0) * dw0
                       + (D[mi][ni][half * 2 + 1] - v1) * dw1;
                    li2 += dw0 * sDM[b] + dw1 * sDM[b + 1];
                }
                qacc[mi * 2 + half] += q;
                lacc[mi * 2 + half] += li2;
            }
        }
    }

#pragma unroll
    for (int i = 0; i < 4; i++) {
        qacc[i] += __shfl_xor_sync(~0u, qacc[i], 1);
        qacc[i] += __shfl_xor_sync(~0u, qacc[i], 2);
        lacc[i] += __shfl_xor_sync(~0u, lacc[i], 1);
        lacc[i] += __shfl_xor_sync(~0u, lacc[i], 2);
    }
    if ((lane & 3) == 0) {
#pragma unroll
        for (int i = 0; i < 4; i++) {
            const int row = wm * 32 + (i >> 1) * 16 + (i & 1) * 8 + (lane >> 2);
            sQ[row * 2 + wn] = qacc[i];
            sL[row * 2 + wn] = lacc[i];
        }
    }
    __syncthreads();
    if (t < 128) {
        const int c = c0 + t;
        if (c < C_DIM) {
            const float Lam = Lam_p[0];
            const float q = sQ[t * 2] + sQ[t * 2 + 1];
            const float li2 = sL[t * 2] + sL[t * 2 + 1];
            g_f4[bi][n][c] = 0.5f * Lam * q + Lam * li2;
        }
    }
}

// ---------------------------------------------------------------------------
// NLL + mean
// ---------------------------------------------------------------------------
__global__ void nll_kernel(const float* __restrict__ ys, const void* __restrict__ labels) {
    __shared__ float sm[128];
    const int n = blockIdx.x, t = threadIdx.x;
    const int sl = g_slot[n];
#define FSUM(c) (g_f4[0][sl][c] + g_f4[1][sl][c] + g_f4[2][sl][c] + g_f4[3][sl][c])
    const float v0 = ys[(size_t)n * C_DIM + t] + FSUM(t);
    const float v1 = ys[(size_t)n * C_DIM + t + 128] + FSUM(t + 128);
    const float v2 = (t + 256 < C_DIM)
                   ? ys[(size_t)n * C_DIM + t + 256] + FSUM(t + 256) : -1e30f;
    float mx = fmaxf(v0, fmaxf(v1, v2));
    sm[t] = mx; __syncthreads();
    for (int s = 64; s > 0; s >>= 1) { if (t < s) sm[t] = fmaxf(sm[t], sm[t + s]); __syncthreads(); }
    const float MX = sm[0]; __syncthreads();
    float e = expf(v0 - MX) + expf(v1 - MX);
    if (t + 256 < C_DIM) e += expf(v2 - MX);
    sm[t] = e; __syncthreads();
    for (int s = 64; s > 0; s >>= 1) { if (t < s) sm[t] += sm[t + s]; __syncthreads(); }
    if (t == 0) {
        const int l = get_label(labels, n, label_is64(labels));
        const float pick = ys[(size_t)n * C_DIM + l] + FSUM(l);
        g_nll[n] = logf(sm[0]) + MX - pick;
    }
#undef FSUM
}

__global__ void mean_kernel(float* __restrict__ out) {
    __shared__ float sm[128];
    const int t = threadIdx.x;
    sm[t] = g_nll[t]; __syncthreads();
    for (int s = 64; s > 0; s >>= 1) { if (t < s) sm[t] += sm[t + s]; __syncthreads(); }
    if (t == 0) out[0] = sm[0] * (1.0f / (float)N_DIM);
}

// ---------------------------------------------------------------------------
// Host launcher
// ---------------------------------------------------------------------------
extern "C" void kernel_launch(void* const* d_in, const int* in_sizes, int n_in,
                              void* d_out, int out_size) {
    const float* W      = (const float*)d_in[0];
    const float* ys     = (const float*)d_in[2];
    const void*  labels = d_in[3];
    const float* Lam    = (const float*)d_in[4];
    const float* ms     = (const float*)d_in[5];
    const float* mt     = (const float*)d_in[6];
    const float* cov    = (const float*)d_in[7];
    float* out = (float*)d_out;

    static int attr_set = 0;
    if (!attr_set) {
        cudaFuncSetAttribute(gemm_kernel, cudaFuncAttributeMaxDynamicSharedMemorySize,
                             SMEM_DYN);
        attr_set = 1;
    }

    prep_labels<<<1, N_DIM>>>(labels);
    conv_w<<<CPAD, 256>>>(W);
    conv_cov<<<dim3(8, 8, N_DIM), dim3(64, 4)>>>(cov, labels);
    gemm_kernel<<<dim3(3, 4, N_DIM), 256, SMEM_DYN>>>(W, labels, Lam, ms, mt);
    nll_kernel<<<N_DIM, 128>>>(ys, labels);
    mean_kernel<<<1, 128>>>(out);
}

// round 9
// speedup vs baseline: 5.8084x; 1.2332x over previous
#include <cuda_runtime.h>
#include <cuda_bf16.h>
#include <cstdint>

#define A_DIM 512
#define C_DIM 345
#define N_DIM 128
#define CPAD  384

// ---------------------------------------------------------------------------
// Scratch (device globals; no allocation allowed)
// ---------------------------------------------------------------------------
__device__ __align__(1024) __nv_bfloat16 g_covT[(size_t)N_DIM * A_DIM * A_DIM]; // [slot][b][a] 67MB
__device__ __align__(1024) __nv_bfloat16 g_Wbf[CPAD * A_DIM];                   // bf16 W, padded rows
__device__ float g_f4[4][N_DIM][CPAD];    // partial f per b-chunk
__device__ float g_nll[N_DIM];
__device__ int   g_slot[N_DIM];
__device__ int   g_first[N_DIM];

// ---------------------------------------------------------------------------
// Helpers
// ---------------------------------------------------------------------------
__device__ __forceinline__ uint32_t smem_u32(const void* p) {
    uint32_t a;
    asm("{ .reg .u64 t; cvta.to.shared.u64 t, %1; cvt.u32.u64 %0, t; }" : "=r"(a) : "l"(p));
    return a;
}
__device__ __forceinline__ void cp16(uint32_t dst, const void* src) {
    asm volatile("cp.async.cg.shared.global [%0], [%1], 16;" :: "r"(dst), "l"(src));
}
#define CP_COMMIT() asm volatile("cp.async.commit_group;")
#define CP_WAIT(N)  asm volatile("cp.async.wait_group %0;" :: "n"(N))

#define LDSM4(r0, r1, r2, r3, addr)                                            \
    asm volatile("ldmatrix.sync.aligned.m8n8.x4.shared.b16 {%0,%1,%2,%3}, [%4];" \
        : "=r"(r0), "=r"(r1), "=r"(r2), "=r"(r3) : "r"(addr))

#define MMA16816(d, a, b0, b1)                                                 \
    asm volatile("mma.sync.aligned.m16n8k16.row.col.f32.bf16.bf16.f32 "        \
        "{%0,%1,%2,%3},{%4,%5,%6,%7},{%8,%9},{%0,%1,%2,%3};"                   \
        : "+f"((d)[0]), "+f"((d)[1]), "+f"((d)[2]), "+f"((d)[3])               \
        : "r"((a)[0]), "r"((a)[1]), "r"((a)[2]), "r"((a)[3]), "r"(b0), "r"(b1))

// Label dtype detection (jax may emit int32 or int64)
__device__ __forceinline__ int label_is64(const void* lp) {
    const long long* p = (const long long*)lp;
    int ok = 1;
#pragma unroll 1
    for (int i = 0; i < 64; i++) {
        long long v = p[i];
        if (v < 0 || v >= C_DIM) { ok = 0; break; }
    }
    return ok;
}
__device__ __forceinline__ int get_label(const void* lp, int n, int is64) {
    return is64 ? (int)((const long long*)lp)[n] : ((const int*)lp)[n];
}

// ---------------------------------------------------------------------------
// prep: slot/first tables
// ---------------------------------------------------------------------------
__global__ void prep_labels(const void* __restrict__ labels) {
    const int t = threadIdx.x;
    const int is64 = label_is64(labels);
    const int ln = get_label(labels, t, is64);
    int slot = t, first = 1;
    for (int m = 0; m < t; m++)
        if (get_label(labels, m, is64) == ln) { slot = m; first = 0; break; }
    g_slot[t] = slot;
    g_first[t] = first;
}

// cast W -> bf16 (pad rows >= C_DIM with zeros)
__global__ void conv_w(const float* __restrict__ Wg) {
    const int c = blockIdx.x, t = threadIdx.x;
    __nv_bfloat162 val;
    if (c < C_DIM) {
        const float2 w = *(const float2*)(Wg + (size_t)c * A_DIM + 2 * t);
        val = __floats2bfloat162_rn(w.x, w.y);
    } else {
        val = __floats2bfloat162_rn(0.f, 0.f);
    }
    *(__nv_bfloat162*)(g_Wbf + (size_t)c * A_DIM + 2 * t) = val;
}

// ---------------------------------------------------------------------------
// conv_cov v2: bandwidth-shaped transpose+cast.
// Tile = [64 a] x [128 b] per CTA, 256 threads.
//   load : float4-coalesced reads of Sigma rows, bf16 scatter into smem[b][a]
//   store: LDS.128 + STG.128, fully coalesced along a.
// covT[slot][b][a] = bf16(Sigma_l[a][b])
// ---------------------------------------------------------------------------
#define CC_PITCH 66   // bf16 elems per smem b-row (64 + 2 pad)

__global__ __launch_bounds__(256, 4)
void conv_cov(const float* __restrict__ cov, const void* __restrict__ labels) {
    const int n = blockIdx.z;
    if (!g_first[n]) return;
    __shared__ __nv_bfloat16 sm[128 * CC_PITCH];
    __shared__ int s_l;
    const int t = threadIdx.x;
    if (t == 0) s_l = get_label(labels, n, label_is64(labels));
    __syncthreads();
    const int l = s_l;

    const int a0 = blockIdx.y * 64;   // 8
    const int b0 = blockIdx.x * 128;  // 4
    const float* S = cov + (size_t)l * A_DIM * A_DIM;

    // load: 64 a-rows x 32 float4 chunks (128 b) = 2048 -> 8 per thread
#pragma unroll
    for (int it = 0; it < 8; it++) {
        const int idx = t + it * 256;
        const int row = idx >> 5;          // a offset 0..63
        const int ch  = idx & 31;          // float4 chunk over b
        const float4 v = *(const float4*)(S + (size_t)(a0 + row) * A_DIM + b0 + ch * 4);
        sm[(ch * 4 + 0) * CC_PITCH + row] = __float2bfloat16(v.x);
        sm[(ch * 4 + 1) * CC_PITCH + row] = __float2bfloat16(v.y);
        sm[(ch * 4 + 2) * CC_PITCH + row] = __float2bfloat16(v.z);
        sm[(ch * 4 + 3) * CC_PITCH + row] = __float2bfloat16(v.w);
    }
    __syncthreads();

    // store: 128 b-rows x 8 chunks(16B = 8 a) = 1024 -> 4 per thread
#pragma unroll
    for (int it = 0; it < 4; it++) {
        const int idx = t + it * 256;
        const int b  = idx >> 3;
        const int ch = idx & 7;
        uint4 v;
        v.x = *(const uint32_t*)&sm[b * CC_PITCH + ch * 8 + 0];
        v.y = *(const uint32_t*)&sm[b * CC_PITCH + ch * 8 + 2];
        v.z = *(const uint32_t*)&sm[b * CC_PITCH + ch * 8 + 4];
        v.w = *(const uint32_t*)&sm[b * CC_PITCH + ch * 8 + 6];
        *(uint4*)(g_covT + ((size_t)n * A_DIM + b0 + b) * A_DIM + a0 + ch * 8) = v;
    }
}

// ---------------------------------------------------------------------------
// Main HMMA GEMM, b-split: CTA = (c-tile, b-chunk, slot).
//   P_chunk = Wbf(c-tile) x SigmaT(slot, b-chunk)   [128 x 128, K=512]
//   v[b] = sum_a Wl[a] * Sigma[a,b] accumulated from staged B tiles (fp32)
//   g_f4[bi][n][c] = 0.5L * sum_b (P-v) dW + L * sum_b dW dM
// ---------------------------------------------------------------------------
#define STG_A   0                       // 3 x 8192
#define STG_B   24576                   // 3 x 8192
#define OFF_WL  49152                   // 512 f32
#define OFF_DM  (OFF_WL + 2048)
#define OFF_Q   (OFF_DM + 2048)         // 128*2 f32
#define OFF_L   (OFF_Q + 1024)
#define OFF_VP  (OFF_L + 1024)          // 256 f32 v partials
#define OFF_LBL (OFF_VP + 1024)
#define SMEM_DYN (OFF_LBL + 16)

__global__ __launch_bounds__(256, 2)
void gemm_kernel(const float* __restrict__ Wg,
                 const void*  __restrict__ labels,
                 const float* __restrict__ Lam_p,
                 const float* __restrict__ ms,
                 const float* __restrict__ mt) {
    extern __shared__ __align__(128) char dsm[];
    const int n = blockIdx.z;
    if (!g_first[n]) return;
    const int bi = blockIdx.y;

    const uint32_t sb = smem_u32(dsm);
    float* sWl = (float*)(dsm + OFF_WL);
    float* sDM = (float*)(dsm + OFF_DM);
    float* sQ  = (float*)(dsm + OFF_Q);
    float* sL  = (float*)(dsm + OFF_L);
    float* sVP = (float*)(dsm + OFF_VP);
    int*   sLb = (int*)(dsm + OFF_LBL);

    const int c0 = blockIdx.x * 128;
    const int t = threadIdx.x;
    const int lane = t & 31, w = t >> 5;
    const int wm = w & 3, wn = w >> 2;

    if (t == 0) sLb[0] = get_label(labels, n, label_is64(labels));
    __syncthreads();
    const int l = sLb[0];
    for (int a = t; a < A_DIM; a += 256) {
        sWl[a] = Wg[(size_t)l * A_DIM + a];
        sDM[a] = mt[(size_t)l * A_DIM + a] - ms[(size_t)l * A_DIM + a];
    }
    __syncthreads();

    // per-lane ldmatrix geometry
    const int lj = lane >> 3, li = lane & 7;
    const int amr0 = wm * 32 + (lj & 1) * 8 + li;
    const int amr1 = amr0 + 16;
    const int akc  = lj >> 1;
    const int asw0 = (amr0 >> 1) & 3, asw1 = (amr1 >> 1) & 3;
    int bnr[4], bsw[4];
#pragma unroll
    for (int np = 0; np < 4; np++) {
        bnr[np] = wn * 64 + np * 16 + (lj >> 1) * 8 + li;
        bsw[np] = (bnr[np] >> 1) & 3;
    }
    const int bkc = lj & 1;

    // v accumulation geometry: thread -> (row, 2 chunks of 8 bf16)
    const int vrow = t >> 1;
    const int vc0  = (t & 1) * 2;
    const uint32_t vof0 = (uint32_t)(vrow * 64 + (((vc0 + 0) ^ ((vrow >> 1) & 3)) << 4));
    const uint32_t vof1 = (uint32_t)(vrow * 64 + (((vc0 + 1) ^ ((vrow >> 1) & 3)) << 4));

    float D[2][8][4];
#pragma unroll
    for (int mi = 0; mi < 2; mi++)
#pragma unroll
        for (int ni = 0; ni < 8; ni++)
#pragma unroll
            for (int e = 0; e < 4; e++) D[mi][ni][e] = 0.f;
    float vacc = 0.f;

    auto stage = [&](int st, int ck) {
        const int a0 = ck * 32;
#pragma unroll
        for (int p = 0; p < 2; p++) {
            const int id = t + 256 * p;
            const int m = id >> 2, ch = id & 3;
            const uint32_t so = (uint32_t)(m * 64 + ((ch ^ ((m >> 1) & 3)) << 4));
            cp16(sb + STG_A + st * 8192 + so,
                 g_Wbf + (size_t)(c0 + m) * A_DIM + a0 + ch * 8);
            cp16(sb + STG_B + st * 8192 + so,
                 g_covT + ((size_t)n * A_DIM + bi * 128 + m) * A_DIM + a0 + ch * 8);
        }
        CP_COMMIT();
    };

    stage(0, 0); stage(1, 1); stage(2, 2);

    int st = 0;
#pragma unroll 1
    for (int k = 0; k < 16; k++) {
        if (k < 14) CP_WAIT(2);
        else if (k == 14) CP_WAIT(1);
        else CP_WAIT(0);
        __syncthreads();

        const uint32_t Ab = sb + STG_A + st * 8192;
        const uint32_t Bb = sb + STG_B + st * 8192;
#pragma unroll
        for (int s = 0; s < 2; s++) {
            uint32_t a0r[4], a1r[4], br[4][4];
            LDSM4(a0r[0], a0r[1], a0r[2], a0r[3],
                  Ab + amr0 * 64 + (((2 * s + akc) ^ asw0) << 4));
            LDSM4(a1r[0], a1r[1], a1r[2], a1r[3],
                  Ab + amr1 * 64 + (((2 * s + akc) ^ asw1) << 4));
#pragma unroll
            for (int np = 0; np < 4; np++)
                LDSM4(br[np][0], br[np][1], br[np][2], br[np][3],
                      Bb + bnr[np] * 64 + (((2 * s + bkc) ^ bsw[np]) << 4));
#pragma unroll
            for (int ni = 0; ni < 8; ni++) {
                const uint32_t b0 = br[ni >> 1][(ni & 1) * 2];
                const uint32_t b1 = br[ni >> 1][(ni & 1) * 2 + 1];
                MMA16816(D[0][ni], a0r, b0, b1);
                MMA16816(D[1][ni], a1r, b0, b1);
            }
        }
        // v side-accumulation from the staged B tile (fp32)
        {
            const int a0 = k * 32;
            const char* Bp = dsm + STG_B + st * 8192;
            const uint4 p0 = *(const uint4*)(Bp + vof0);
            const uint4 p1 = *(const uint4*)(Bp + vof1);
            const __nv_bfloat162* h0 = (const __nv_bfloat162*)&p0;
            const __nv_bfloat162* h1 = (const __nv_bfloat162*)&p1;
            const float* wl0 = sWl + a0 + vc0 * 8;
#pragma unroll
            for (int j = 0; j < 4; j++) {
                const float2 f0 = __bfloat1622float2(h0[j]);
                const float2 f1 = __bfloat1622float2(h1[j]);
                vacc += f0.x * wl0[2 * j] + f0.y * wl0[2 * j + 1];
                vacc += f1.x * wl0[8 + 2 * j] + f1.y * wl0[8 + 2 * j + 1];
            }
        }
        __syncthreads();
        if (k + 3 < 16) stage(st, k + 3);
        st = (st == 2) ? 0 : st + 1;
    }

    sVP[t] = vacc;
    __syncthreads();

    // epilogue: contract P-frags against dw, v, dM
    float qacc[4] = {0, 0, 0, 0}, lacc[4] = {0, 0, 0, 0};
#pragma unroll
    for (int mi = 0; mi < 2; mi++) {
        const int crb = c0 + wm * 32 + mi * 16 + (lane >> 2);
#pragma unroll
        for (int half = 0; half < 2; half++) {
            const int cr = crb + half * 8;
            if (cr < C_DIM) {
                const float* wrow = Wg + (size_t)cr * A_DIM;
                float q = 0.f, li2 = 0.f;
#pragma unroll
                for (int ni = 0; ni < 8; ni++) {
                    const int bl = wn * 64 + ni * 8 + (lane & 3) * 2;  // local b
                    const int b  = bi * 128 + bl;                      // global b
                    const float2 wv = *(const float2*)(wrow + b);
                    const float dw0 = wv.x - sWl[b], dw1 = wv.y - sWl[b + 1];
                    const float v0 = sVP[2 * bl] + sVP[2 * bl + 1];
                    const float v1 = sVP[2 * bl + 2] + sVP[2 * bl + 3];
                    q += (D[mi][ni][half * 2 + 0] - v0) * dw0
                       + (D[mi][ni][half * 2 + 1] - v1) * dw1;
                    li2 += dw0 * sDM[b] + dw1 * sDM[b + 1];
                }
                qacc[mi * 2 + half] += q;
                lacc[mi * 2 + half] += li2;
            }
        }
    }

#pragma unroll
    for (int i = 0; i < 4; i++) {
        qacc[i] += __shfl_xor_sync(~0u, qacc[i], 1);
        qacc[i] += __shfl_xor_sync(~0u, qacc[i], 2);
        lacc[i] += __shfl_xor_sync(~0u, lacc[i], 1);
        lacc[i] += __shfl_xor_sync(~0u, lacc[i], 2);
    }
    if ((lane & 3) == 0) {
#pragma unroll
        for (int i = 0; i < 4; i++) {
            const int row = wm * 32 + (i >> 1) * 16 + (i & 1) * 8 + (lane >> 2);
            sQ[row * 2 + wn] = qacc[i];
            sL[row * 2 + wn] = lacc[i];
        }
    }
    __syncthreads();
    if (t < 128) {
        const int c = c0 + t;
        if (c < C_DIM) {
            const float Lam = Lam_p[0];
            const float q = sQ[t * 2] + sQ[t * 2 + 1];
            const float li2 = sL[t * 2] + sL[t * 2 + 1];
            g_f4[bi][n][c] = 0.5f * Lam * q + Lam * li2;
        }
    }
}

// ---------------------------------------------------------------------------
// NLL + mean
// ---------------------------------------------------------------------------
__global__ void nll_kernel(const float* __restrict__ ys, const void* __restrict__ labels) {
    __shared__ float sm[128];
    const int n = blockIdx.x, t = threadIdx.x;
    const int sl = g_slot[n];
#define FSUM(c) (g_f4[0][sl][c] + g_f4[1][sl][c] + g_f4[2][sl][c] + g_f4[3][sl][c])
    const float v0 = ys[(size_t)n * C_DIM + t] + FSUM(t);
    const float v1 = ys[(size_t)n * C_DIM + t + 128] + FSUM(t + 128);
    const float v2 = (t + 256 < C_DIM)
                   ? ys[(size_t)n * C_DIM + t + 256] + FSUM(t + 256) : -1e30f;
    float mx = fmaxf(v0, fmaxf(v1, v2));
    sm[t] = mx; __syncthreads();
    for (int s = 64; s > 0; s >>= 1) { if (t < s) sm[t] = fmaxf(sm[t], sm[t + s]); __syncthreads(); }
    const float MX = sm[0]; __syncthreads();
    float e = expf(v0 - MX) + expf(v1 - MX);
    if (t + 256 < C_DIM) e += expf(v2 - MX);
    sm[t] = e; __syncthreads();
    for (int s = 64; s > 0; s >>= 1) { if (t < s) sm[t] += sm[t + s]; __syncthreads(); }
    if (t == 0) {
        const int l = get_label(labels, n, label_is64(labels));
        const float pick = ys[(size_t)n * C_DIM + l] + FSUM(l);
        g_nll[n] = logf(sm[0]) + MX - pick;
    }
#undef FSUM
}

__global__ void mean_kernel(float* __restrict__ out) {
    __shared__ float sm[128];
    const int t = threadIdx.x;
    sm[t] = g_nll[t]; __syncthreads();
    for (int s = 64; s > 0; s >>= 1) { if (t < s) sm[t] += sm[t + s]; __syncthreads(); }
    if (t == 0) out[0] = sm[0] * (1.0f / (float)N_DIM);
}

// ---------------------------------------------------------------------------
// Host launcher
// ---------------------------------------------------------------------------
extern "C" void kernel_launch(void* const* d_in, const int* in_sizes, int n_in,
                              void* d_out, int out_size) {
    const float* W      = (const float*)d_in[0];
    const float* ys     = (const float*)d_in[2];
    const void*  labels = d_in[3];
    const float* Lam    = (const float*)d_in[4];
    const float* ms     = (const float*)d_in[5];
    const float* mt     = (const float*)d_in[6];
    const float* cov    = (const float*)d_in[7];
    float* out = (float*)d_out;

    static int attr_set = 0;
    if (!attr_set) {
        cudaFuncSetAttribute(gemm_kernel, cudaFuncAttributeMaxDynamicSharedMemorySize,
                             SMEM_DYN);
        attr_set = 1;
    }

    prep_labels<<<1, N_DIM>>>(labels);
    conv_w<<<CPAD, 256>>>(W);
    conv_cov<<<dim3(4, 8, N_DIM), 256>>>(cov, labels);
    gemm_kernel<<<dim3(3, 4, N_DIM), 256, SMEM_DYN>>>(W, labels, Lam, ms, mt);
    nll_kernel<<<N_DIM, 128>>>(ys, labels);
    mean_kernel<<<1, 128>>>(out);
}